// round 2
// baseline (speedup 1.0000x reference)
#include <cuda_runtime.h>
#include <math.h>

#define BSZ 1024
#define T1  127
#define HD  128
#define HE  128
#define ZD  512
#define GMAX 7
#define NCTA 147   // 147*7 = 1029 >= 1024

// global scratch (allowed: __device__ arrays)
__device__ float g_prex[(size_t)BSZ * T1 * HE];   // 66.6 MB, L2-resident
__device__ float g_px2[BSZ * T1];

static __device__ __forceinline__ float ex2f(float x){ float r; asm("ex2.approx.f32 %0, %1;" : "=f"(r) : "f"(x)); return r; }
static __device__ __forceinline__ float rcpf(float x){ float r; asm("rcp.approx.f32 %0, %1;" : "=f"(r) : "f"(x)); return r; }

// tanh(x) = sign(x)*(1 - 2e/(1+e)), e = exp(-2|x|)
static __device__ __forceinline__ float tanh_fast(float x){
    float e = ex2f(fabsf(x) * -2.8853900817779268f);
    float r = rcpf(1.0f + e);
    float t = fmaf(-2.0f * (e * r), 1.0f, 1.0f);
    return copysignf(t, x);
}
static __device__ __forceinline__ float sigmoid_fast(float x){
    float e = ex2f(x * -1.4426950408889634f);
    return rcpf(1.0f + e);
}

// ---------------------------------------------------------------------------
// Prepass: pre_x[b,t,e] = X[b,t,:]@W1_x + b1[e];  px2[b,t] = X[b,t,:].Wfc[:128]
// one CTA per batch; W1_x (64KB) + X[b] (63.5KB) in smem
// ---------------------------------------------------------------------------
#define PRE_SMEM ((HD*HE + T1*HE) * 4)

__global__ void __launch_bounds__(256, 1)
prex_kernel(const float* __restrict__ X, const float* __restrict__ W1,
            const float* __restrict__ b1, const float* __restrict__ Wfc)
{
    extern __shared__ float sm[];
    float* sW = sm;            // 128*128
    float* sX = sm + HD * HE;  // 127*128
    int b = blockIdx.x;
    int tid = threadIdx.x, lane = tid & 31, wid = tid >> 5;
    const float* Xb = X + (size_t)b * T1 * HE;

    for (int i = tid; i < HD * HE; i += 256) sW[i] = W1[2 * HD * HE + i];
    for (int i = tid; i < T1 * HE; i += 256) sX[i] = Xb[i];
    __syncthreads();

    int e = tid & 127, th = tid >> 7;
    float b1e = b1[e];
    for (int t = th; t < T1; t += 2) {
        float acc = 0.f;
        const float* xr = sX + t * HE;
        #pragma unroll 8
        for (int k = 0; k < HE; k++) acc = fmaf(xr[k], sW[k * HE + e], acc);
        g_prex[((size_t)b * T1 + t) * HE + e] = acc + b1e;
    }

    // px2
    float4 wf = ((const float4*)Wfc)[lane];
    for (int t = wid; t < T1; t += 8) {
        float4 x = ((const float4*)(sX + t * HE))[lane];
        float p = x.x * wf.x + x.y * wf.y + x.z * wf.z + x.w * wf.w;
        #pragma unroll
        for (int m = 16; m; m >>= 1) p += __shfl_xor_sync(0xffffffffu, p, m);
        if (lane == 0) g_px2[b * T1 + t] = p;
    }
}

// ---------------------------------------------------------------------------
// Main persistent kernel: 147 CTAs x 7 batches, 127 steps
// ---------------------------------------------------------------------------
// smem float offsets
#define O_W1   0                      // 2*128*128 = 32768
#define O_Z    32768                  // 3584 (phase-A partials 2x896 / z 7x512)
#define O_D    (O_Z + 3584)           // 896
#define O_C    (O_D + 896)            // 896
#define O_BETA (O_C + 896)            // 896
#define O_PX2  (O_BETA + 896)         // 896
#define O_SB   (O_PX2 + 896)          // 8
#define MAIN_SMEM ((O_SB + 8) * 4)    // 159,776 B

__global__ void __launch_bounds__(256, 1)
decoder_kernel(const float* __restrict__ X, const float* __restrict__ yprev,
               const float* __restrict__ W1, const float* __restrict__ W2,
               const float* __restrict__ b2, const float* __restrict__ Wfc,
               const float* __restrict__ bfc, const float* __restrict__ Wx,
               const float* __restrict__ Wh, const float* __restrict__ bl,
               const float* __restrict__ Wf, const float* __restrict__ bf,
               float* __restrict__ out)
{
    extern __shared__ float sm[];
    float* sW1   = sm + O_W1;
    float* sz    = sm + O_Z;
    float* sd    = sm + O_D;
    float* sc    = sm + O_C;
    float* sbeta = sm + O_BETA;
    float* spx2  = sm + O_PX2;
    float* ssb   = sm + O_SB;

    int tid = threadIdx.x, lane = tid & 31, wid = tid >> 5;
    int b0 = blockIdx.x * GMAX;
    if (b0 >= BSZ) return;
    int nb = min(GMAX, BSZ - b0);

    for (int i = tid; i < 2 * HD * HE; i += 256) sW1[i] = W1[i];
    for (int i = tid; i < nb * 128; i += 256) {
        int b = i >> 7, tp = i & 127;
        spx2[i] = (tp < T1) ? g_px2[(b0 + b) * T1 + tp] : 0.f;
    }
    for (int i = tid; i < nb * 128; i += 256) {
        float x00 = X[(size_t)(b0 + (i >> 7)) * T1 * HE];
        sd[i] = x00; sc[i] = x00;
    }
    float b2v  = b2[0];
    float bfcv = bfc[0];
    float wfcy = Wfc[HE];
    float wx1 = Wx[tid], wx2 = Wx[tid + 256];
    float bl1 = bl[tid], bl2 = bl[tid + 256];
    __syncthreads();

    for (int t = 0; t < T1; t++) {
        // ---- Phase A: v partials = d@W1_d + c@W1_c, 2-way k-split ----
        {
            int e = tid & 127, h = tid >> 7;
            const float* wd = sW1 + e;
            const float* wc = sW1 + 128 * 128 + e;
            float acc[GMAX];
            #pragma unroll
            for (int b = 0; b < GMAX; b++) acc[b] = 0.f;
            int kbase = h * 64;
            for (int kk = 0; kk < 64; kk += 4) {
                int k = kbase + kk;
                float w0 = wd[k*128], w1 = wd[(k+1)*128], w2w = wd[(k+2)*128], w3 = wd[(k+3)*128];
                float u0 = wc[k*128], u1 = wc[(k+1)*128], u2 = wc[(k+2)*128], u3 = wc[(k+3)*128];
                #pragma unroll
                for (int b = 0; b < GMAX; b++) if (b < nb) {
                    float4 dv = *(const float4*)(sd + b*128 + k);
                    float4 cv = *(const float4*)(sc + b*128 + k);
                    float a = acc[b];
                    a = fmaf(dv.x, w0, a); a = fmaf(dv.y, w1, a);
                    a = fmaf(dv.z, w2w, a); a = fmaf(dv.w, w3, a);
                    a = fmaf(cv.x, u0, a); a = fmaf(cv.y, u1, a);
                    a = fmaf(cv.z, u2, a); a = fmaf(cv.w, u3, a);
                    acc[b] = a;
                }
            }
            #pragma unroll
            for (int b = 0; b < GMAX; b++) if (b < nb) sz[h*896 + b*128 + e] = acc[b];
        }
        __syncthreads();

        // ---- Phase B: beta over t', s = sum beta*px2 (lane-deferred reduce) ----
        if (wid < nb) {
            int b = wid;
            bool last = (t == T1 - 1);
            float4 p0 = ((const float4*)(sz + b*128))[lane];
            float4 p1 = ((const float4*)(sz + 896 + b*128))[lane];
            float4 vr = make_float4(p0.x+p1.x, p0.y+p1.y, p0.z+p1.z, p0.w+p1.w);
            float4 w2r = ((const float4*)W2)[lane];
            const float4* pxb = (const float4*)(g_prex + (size_t)(b0 + b) * T1 * HE);
            float s_l = 0.f, q = 0.f;
            #pragma unroll 4
            for (int tp = 0; tp < T1; tp++) {
                float4 px = pxb[tp*32 + lane];
                float h0 = tanh_fast(px.x + vr.x);
                float h1 = tanh_fast(px.y + vr.y);
                float h2 = tanh_fast(px.z + vr.z);
                float h3 = tanh_fast(px.w + vr.w);
                float pl = h0*w2r.x;
                pl = fmaf(h1, w2r.y, pl);
                pl = fmaf(h2, w2r.z, pl);
                pl = fmaf(h3, w2r.w, pl);
                float p2 = spx2[b*128 + tp];
                s_l = fmaf(pl, p2, s_l);
                q += p2;
                if (last) {
                    float bs = pl;
                    #pragma unroll
                    for (int m = 16; m; m >>= 1) bs += __shfl_xor_sync(0xffffffffu, bs, m);
                    if (lane == 0) sbeta[b*128 + tp] = bs + b2v;
                }
            }
            #pragma unroll
            for (int m = 16; m; m >>= 1) s_l += __shfl_xor_sync(0xffffffffu, s_l, m);
            if (lane == 0) ssb[b] = fmaf(b2v, q, s_l);
        }
        __syncthreads();

        // ---- Phase C: z[b][j] = ytilde*Wx[j] + d@Wh[:,j] + bl[j] ----
        {
            int j1 = tid, j2 = tid + 256;
            float a1[GMAX], a2[GMAX];
            #pragma unroll
            for (int b = 0; b < GMAX; b++) if (b < nb) {
                float yt = fmaf(yprev[(size_t)(b0 + b) * T1 + t], wfcy, ssb[b] + bfcv);
                a1[b] = fmaf(yt, wx1, bl1);
                a2[b] = fmaf(yt, wx2, bl2);
            }
            for (int k = 0; k < 128; k += 4) {
                const float* whp = Wh + (size_t)k * ZD;
                float w10 = whp[j1], w11 = whp[512 + j1], w12 = whp[1024 + j1], w13 = whp[1536 + j1];
                float w20 = whp[j2], w21 = whp[512 + j2], w22 = whp[1024 + j2], w23 = whp[1536 + j2];
                #pragma unroll
                for (int b = 0; b < GMAX; b++) if (b < nb) {
                    float4 dv = *(const float4*)(sd + b*128 + k);
                    float x1 = a1[b], x2 = a2[b];
                    x1 = fmaf(dv.x, w10, x1); x1 = fmaf(dv.y, w11, x1);
                    x1 = fmaf(dv.z, w12, x1); x1 = fmaf(dv.w, w13, x1);
                    x2 = fmaf(dv.x, w20, x2); x2 = fmaf(dv.y, w21, x2);
                    x2 = fmaf(dv.z, w22, x2); x2 = fmaf(dv.w, w23, x2);
                    a1[b] = x1; a2[b] = x2;
                }
            }
            __syncthreads();   // sz (phase-A partials) fully consumed; now reuse as z
            #pragma unroll
            for (int b = 0; b < GMAX; b++) if (b < nb) {
                sz[b*512 + j1] = a1[b];
                sz[b*512 + j2] = a2[b];
            }
        }
        __syncthreads();

        // ---- Gates ----
        for (int idx = tid; idx < nb * 128; idx += 256) {
            int b = idx >> 7, k = idx & 127;
            const float* zb = sz + b * 512;
            float zi = zb[k], zf = zb[128 + k], zg = zb[256 + k], zo = zb[384 + k];
            float cn = fmaf(sigmoid_fast(zf), sc[idx], sigmoid_fast(zi) * tanh_fast(zg));
            sc[idx] = cn;
            sd[idx] = sigmoid_fast(zo) * tanh_fast(cn);
        }
        __syncthreads();
    }

    // ---- Epilogue: ctx from final beta; out = d.Wf[:128] + ctx.Wf[128:] + bf ----
    if (wid < nb) {
        int b = wid;
        const float4* Xb = (const float4*)(X + (size_t)(b0 + b) * T1 * HE);
        float cx = 0.f, cy = 0.f, cz = 0.f, cw = 0.f;
        for (int tp = 0; tp < T1; tp++) {
            float bb = sbeta[b*128 + tp];
            float4 xv = Xb[tp*32 + lane];
            cx = fmaf(bb, xv.x, cx); cy = fmaf(bb, xv.y, cy);
            cz = fmaf(bb, xv.z, cz); cw = fmaf(bb, xv.w, cw);
        }
        float4 wfc2 = ((const float4*)(Wf + 128))[lane];
        float4 wfd  = ((const float4*)Wf)[lane];
        float4 dv   = ((const float4*)(sd + b*128))[lane];
        float r = cx*wfc2.x + cy*wfc2.y + cz*wfc2.z + cw*wfc2.w;
        r = fmaf(dv.x, wfd.x, r); r = fmaf(dv.y, wfd.y, r);
        r = fmaf(dv.z, wfd.z, r); r = fmaf(dv.w, wfd.w, r);
        #pragma unroll
        for (int m = 16; m; m >>= 1) r += __shfl_xor_sync(0xffffffffu, r, m);
        if (lane == 0) out[b0 + b] = r + bf[0];
    }
}

extern "C" void kernel_launch(void* const* d_in, const int* in_sizes, int n_in,
                              void* d_out, int out_size)
{
    const float* X    = (const float*)d_in[0];
    const float* yprev= (const float*)d_in[1];
    const float* W1   = (const float*)d_in[2];
    const float* b1   = (const float*)d_in[3];
    const float* W2   = (const float*)d_in[4];
    const float* b2   = (const float*)d_in[5];
    const float* Wfc  = (const float*)d_in[6];
    const float* bfc  = (const float*)d_in[7];
    const float* Wx   = (const float*)d_in[8];
    const float* Wh   = (const float*)d_in[9];
    const float* bl   = (const float*)d_in[10];
    const float* Wf   = (const float*)d_in[11];
    const float* bf   = (const float*)d_in[12];
    float* out = (float*)d_out;

    cudaFuncSetAttribute(prex_kernel, cudaFuncAttributeMaxDynamicSharedMemorySize, PRE_SMEM);
    cudaFuncSetAttribute(decoder_kernel, cudaFuncAttributeMaxDynamicSharedMemorySize, MAIN_SMEM);

    prex_kernel<<<BSZ, 256, PRE_SMEM>>>(X, W1, b1, Wfc);
    decoder_kernel<<<NCTA, 256, MAIN_SMEM>>>(X, yprev, W1, W2, b2, Wfc, bfc,
                                             Wx, Wh, bl, Wf, bf, out);
}

// round 3
// speedup vs baseline: 3.0706x; 3.0706x over previous
#include <cuda_runtime.h>
#include <math.h>

#define BSZ 1024
#define T1  127
#define TP  128      // padded time dim for g_prex
#define HD  128
#define HE  128
#define ZD  512
#define GMAX 7
#define NCTA 147     // 147*7 = 1029 >= 1024

// global scratch (allowed: __device__ arrays); zero-initialized at module load
__device__ float g_prex[(size_t)BSZ * TP * HE];   // 67 MB, L2-resident
__device__ float g_px2[BSZ * T1];

static __device__ __forceinline__ float tanh_ap(float x){
    float r; asm("tanh.approx.f32 %0, %1;" : "=f"(r) : "f"(x)); return r;
}
static __device__ __forceinline__ float sig_ap(float x){
    return fmaf(0.5f, tanh_ap(0.5f * x), 0.5f);
}

// ---------------------------------------------------------------------------
// Prepass: pre_x[b,t,e] = X[b,t,:]@W1_x + b1[e] (t padded to 128, row127 = 0)
//          px2[b,t]     = X[b,t,:].Wfc[:128]
// ---------------------------------------------------------------------------
#define PRE_SMEM ((HD*HE + T1*HE) * 4)

__global__ void __launch_bounds__(256, 1)
prex_kernel(const float* __restrict__ X, const float* __restrict__ W1,
            const float* __restrict__ b1, const float* __restrict__ Wfc)
{
    extern __shared__ float sm[];
    float* sW = sm;            // 128*128
    float* sX = sm + HD * HE;  // 127*128
    int b = blockIdx.x;
    int tid = threadIdx.x, lane = tid & 31, wid = tid >> 5;
    const float* Xb = X + (size_t)b * T1 * HE;

    for (int i = tid; i < HD * HE; i += 256) sW[i] = W1[2 * HD * HE + i];
    for (int i = tid; i < T1 * HE; i += 256) sX[i] = Xb[i];
    __syncthreads();

    int e = tid & 127, th = tid >> 7;
    float b1e = b1[e];
    for (int t = th; t < T1; t += 2) {
        float acc = 0.f;
        const float* xr = sX + t * HE;
        #pragma unroll 8
        for (int k = 0; k < HE; k++) acc = fmaf(xr[k], sW[k * HE + e], acc);
        g_prex[((size_t)b * TP + t) * HE + e] = acc + b1e;
    }
    if (tid < 128) g_prex[((size_t)b * TP + 127) * HE + tid] = 0.f;  // pad row

    float4 wf = ((const float4*)Wfc)[lane];
    for (int t = wid; t < T1; t += 8) {
        float4 x = ((const float4*)(sX + t * HE))[lane];
        float p = x.x * wf.x + x.y * wf.y + x.z * wf.z + x.w * wf.w;
        #pragma unroll
        for (int m = 16; m; m >>= 1) p += __shfl_xor_sync(0xffffffffu, p, m);
        if (lane == 0) g_px2[b * T1 + t] = p;
    }
}

// ---------------------------------------------------------------------------
// Main persistent kernel: 147 CTAs x 7 batches x 512 threads, 127 steps
// ---------------------------------------------------------------------------
// smem float offsets
#define O_W1   0                      // 2*128*128 = 32768
#define O_VA   32768                  // A partials [4][7][128] = 3584
#define O_ZP   (O_VA + 3584)          // C partials [4][7][512] = 14336
#define O_D    (O_ZP + 14336)         // 896
#define O_C    (O_D + 896)            // 896
#define O_BETA (O_C + 896)            // 896
#define O_PX2  (O_BETA + 896)         // 896
#define O_YP   (O_PX2 + 896)          // 896 (yprev, stride 128)
#define O_W2   (O_YP + 896)           // 128
#define O_WX   (O_W2 + 128)           // 512
#define O_BL   (O_WX + 512)           // 512
#define O_SSB  (O_BL + 512)           // 16
#define O_SQ   (O_SSB + 16)           // 8
#define MAIN_FLOATS (O_SQ + 8)
#define MAIN_SMEM (MAIN_FLOATS * 4)   // 225,376 B

struct Ctx {
    float* sW1; float* sva; float* szp; float* sd; float* sc; float* sbeta;
    float* spx2; float* syp; float* sW2; float* sWx; float* sbl; float* ssb; float* sq;
};

static __device__ __forceinline__ void phaseB(const Ctx& cx, int b0, int b, int half,
                                              int lane, bool last, float b2v)
{
    float4 a0 = ((const float4*)(cx.sva + 0*896 + b*128))[lane];
    float4 a1 = ((const float4*)(cx.sva + 1*896 + b*128))[lane];
    float4 a2 = ((const float4*)(cx.sva + 2*896 + b*128))[lane];
    float4 a3 = ((const float4*)(cx.sva + 3*896 + b*128))[lane];
    float4 vr = make_float4(a0.x+a1.x+a2.x+a3.x, a0.y+a1.y+a2.y+a3.y,
                            a0.z+a1.z+a2.z+a3.z, a0.w+a1.w+a2.w+a3.w);
    float4 w2r = ((const float4*)cx.sW2)[lane];
    const float4* pxb = ((const float4*)(g_prex + (size_t)(b0 + b) * TP * HE)) + lane;
    const float* px2b = cx.spx2 + b * 128;
    float s_l = 0.f;
    int tp0 = half * 64;
    #pragma unroll 1
    for (int tc = 0; tc < 64; tc += 4) {
        int tp = tp0 + tc;
        float4 p0 = pxb[(tp+0)*32];
        float4 p1 = pxb[(tp+1)*32];
        float4 p2 = pxb[(tp+2)*32];
        float4 p3 = pxb[(tp+3)*32];
        float pl0 = w2r.x*tanh_ap(p0.x+vr.x); pl0 = fmaf(w2r.y, tanh_ap(p0.y+vr.y), pl0);
        pl0 = fmaf(w2r.z, tanh_ap(p0.z+vr.z), pl0); pl0 = fmaf(w2r.w, tanh_ap(p0.w+vr.w), pl0);
        float pl1 = w2r.x*tanh_ap(p1.x+vr.x); pl1 = fmaf(w2r.y, tanh_ap(p1.y+vr.y), pl1);
        pl1 = fmaf(w2r.z, tanh_ap(p1.z+vr.z), pl1); pl1 = fmaf(w2r.w, tanh_ap(p1.w+vr.w), pl1);
        float pl2 = w2r.x*tanh_ap(p2.x+vr.x); pl2 = fmaf(w2r.y, tanh_ap(p2.y+vr.y), pl2);
        pl2 = fmaf(w2r.z, tanh_ap(p2.z+vr.z), pl2); pl2 = fmaf(w2r.w, tanh_ap(p2.w+vr.w), pl2);
        float pl3 = w2r.x*tanh_ap(p3.x+vr.x); pl3 = fmaf(w2r.y, tanh_ap(p3.y+vr.y), pl3);
        pl3 = fmaf(w2r.z, tanh_ap(p3.z+vr.z), pl3); pl3 = fmaf(w2r.w, tanh_ap(p3.w+vr.w), pl3);
        s_l = fmaf(pl0, px2b[tp+0], s_l);
        s_l = fmaf(pl1, px2b[tp+1], s_l);
        s_l = fmaf(pl2, px2b[tp+2], s_l);
        s_l = fmaf(pl3, px2b[tp+3], s_l);
        if (last) {
            float r0 = pl0, r1 = pl1, r2 = pl2, r3 = pl3;
            #pragma unroll
            for (int m = 16; m; m >>= 1) {
                r0 += __shfl_xor_sync(0xffffffffu, r0, m);
                r1 += __shfl_xor_sync(0xffffffffu, r1, m);
                r2 += __shfl_xor_sync(0xffffffffu, r2, m);
                r3 += __shfl_xor_sync(0xffffffffu, r3, m);
            }
            if (lane == 0) {
                cx.sbeta[b*128 + tp+0] = r0 + b2v;
                cx.sbeta[b*128 + tp+1] = r1 + b2v;
                cx.sbeta[b*128 + tp+2] = r2 + b2v;
                cx.sbeta[b*128 + tp+3] = r3 + b2v;
            }
        }
    }
    #pragma unroll
    for (int m = 16; m; m >>= 1) s_l += __shfl_xor_sync(0xffffffffu, s_l, m);
    if (lane == 0) cx.ssb[2*b + half] = s_l;
}

static __device__ __forceinline__ void phaseC(const Ctx& cx, const float* __restrict__ Wh,
                                              int tid, int nb)
{
    int jg = tid & 127, h = tid >> 7, kb = h * 32;
    const float* whp = Wh + (size_t)kb * ZD + jg * 4;
    float4 a[GMAX];
    #pragma unroll
    for (int b = 0; b < GMAX; b++) a[b] = make_float4(0.f, 0.f, 0.f, 0.f);
    #pragma unroll 2
    for (int kk = 0; kk < 32; kk += 4) {
        float4 w0 = *(const float4*)(whp + (size_t)(kk+0) * ZD);
        float4 w1 = *(const float4*)(whp + (size_t)(kk+1) * ZD);
        float4 w2 = *(const float4*)(whp + (size_t)(kk+2) * ZD);
        float4 w3 = *(const float4*)(whp + (size_t)(kk+3) * ZD);
        #pragma unroll
        for (int b = 0; b < GMAX; b++) if (b < nb) {
            float4 dv = *(const float4*)(cx.sd + b*128 + kb + kk);
            float4 ab = a[b];
            ab.x = fmaf(dv.x, w0.x, ab.x); ab.y = fmaf(dv.x, w0.y, ab.y);
            ab.z = fmaf(dv.x, w0.z, ab.z); ab.w = fmaf(dv.x, w0.w, ab.w);
            ab.x = fmaf(dv.y, w1.x, ab.x); ab.y = fmaf(dv.y, w1.y, ab.y);
            ab.z = fmaf(dv.y, w1.z, ab.z); ab.w = fmaf(dv.y, w1.w, ab.w);
            ab.x = fmaf(dv.z, w2.x, ab.x); ab.y = fmaf(dv.z, w2.y, ab.y);
            ab.z = fmaf(dv.z, w2.z, ab.z); ab.w = fmaf(dv.z, w2.w, ab.w);
            ab.x = fmaf(dv.w, w3.x, ab.x); ab.y = fmaf(dv.w, w3.y, ab.y);
            ab.z = fmaf(dv.w, w3.z, ab.z); ab.w = fmaf(dv.w, w3.w, ab.w);
            a[b] = ab;
        }
    }
    #pragma unroll
    for (int b = 0; b < GMAX; b++) if (b < nb)
        *(float4*)(cx.szp + h*3584 + b*512 + jg*4) = a[b];
}

__global__ void __launch_bounds__(512, 1)
decoder_kernel(const float* __restrict__ X, const float* __restrict__ yprev,
               const float* __restrict__ W1, const float* __restrict__ W2,
               const float* __restrict__ b2, const float* __restrict__ Wfc,
               const float* __restrict__ bfc, const float* __restrict__ Wx,
               const float* __restrict__ Wh, const float* __restrict__ bl,
               const float* __restrict__ Wf, const float* __restrict__ bf,
               float* __restrict__ out)
{
    extern __shared__ float sm[];
    Ctx cx;
    cx.sW1 = sm + O_W1;  cx.sva = sm + O_VA;  cx.szp = sm + O_ZP;
    cx.sd = sm + O_D;    cx.sc = sm + O_C;    cx.sbeta = sm + O_BETA;
    cx.spx2 = sm + O_PX2; cx.syp = sm + O_YP; cx.sW2 = sm + O_W2;
    cx.sWx = sm + O_WX;  cx.sbl = sm + O_BL;  cx.ssb = sm + O_SSB; cx.sq = sm + O_SQ;

    int tid = threadIdx.x, lane = tid & 31, wid = tid >> 5;
    int b0 = blockIdx.x * GMAX;
    if (b0 >= BSZ) return;
    int nb = min(GMAX, BSZ - b0);

    for (int i = tid; i < 2 * HD * HE; i += 512) cx.sW1[i] = W1[i];
    if (tid < 128) cx.sW2[tid] = W2[tid];
    if (tid < 512) { cx.sWx[tid] = Wx[tid]; cx.sbl[tid] = bl[tid]; }
    for (int i = tid; i < nb * 128; i += 512) {
        int b = i >> 7, tp = i & 127;
        cx.spx2[i] = (tp < T1) ? g_px2[(b0 + b) * T1 + tp] : 0.f;
        cx.syp[i]  = (tp < T1) ? yprev[(size_t)(b0 + b) * T1 + tp] : 0.f;
        float x00 = X[(size_t)(b0 + b) * T1 * HE];
        cx.sd[i] = x00; cx.sc[i] = x00;
    }
    float b2v  = b2[0];
    float bfcv = bfc[0];
    float wfcy = Wfc[HE];
    __syncthreads();
    if (wid < nb) {   // step-invariant q_b = sum_t px2[b,t]
        const float* p = cx.spx2 + wid * 128;
        float v = p[lane] + p[lane+32] + p[lane+64] + p[lane+96];
        #pragma unroll
        for (int m = 16; m; m >>= 1) v += __shfl_xor_sync(0xffffffffu, v, m);
        if (lane == 0) cx.sq[wid] = v;
    }

    for (int t = 0; t < T1; t++) {
        // ---- Phase A: v partials = d@W1_d + c@W1_c, 4-way k-split ----
        {
            int e = tid & 127, h = tid >> 7, kb = h * 32;
            const float* wd = cx.sW1 + e;
            const float* wc = cx.sW1 + 128 * 128 + e;
            float acc[GMAX];
            #pragma unroll
            for (int b = 0; b < GMAX; b++) acc[b] = 0.f;
            #pragma unroll 2
            for (int kk = 0; kk < 32; kk += 4) {
                int k = kb + kk;
                float w0 = wd[k*128], w1 = wd[(k+1)*128], w2w = wd[(k+2)*128], w3 = wd[(k+3)*128];
                float u0 = wc[k*128], u1 = wc[(k+1)*128], u2 = wc[(k+2)*128], u3 = wc[(k+3)*128];
                #pragma unroll
                for (int b = 0; b < GMAX; b++) if (b < nb) {
                    float4 dv = *(const float4*)(cx.sd + b*128 + k);
                    float4 cv = *(const float4*)(cx.sc + b*128 + k);
                    float a = acc[b];
                    a = fmaf(dv.x, w0, a); a = fmaf(dv.y, w1, a);
                    a = fmaf(dv.z, w2w, a); a = fmaf(dv.w, w3, a);
                    a = fmaf(cv.x, u0, a); a = fmaf(cv.y, u1, a);
                    a = fmaf(cv.z, u2, a); a = fmaf(cv.w, u3, a);
                    acc[b] = a;
                }
            }
            #pragma unroll
            for (int b = 0; b < GMAX; b++) if (b < nb) cx.sva[h*896 + b*128 + e] = acc[b];
        }
        __syncthreads();

        // ---- Merged B (attention, MUFU) + C (d@Wh, FMA) with warp stagger ----
        {
            bool doB = (wid < 2 * nb);
            int b = wid >> 1, half = wid & 1;
            bool last = (t == T1 - 1);
            if (wid & 1) {
                phaseC(cx, Wh, tid, nb);
                if (doB) phaseB(cx, b0, b, half, lane, last, b2v);
            } else {
                if (doB) phaseB(cx, b0, b, half, lane, last, b2v);
                phaseC(cx, Wh, tid, nb);
            }
        }
        __syncthreads();

        // ---- Phase D: assemble z, gates, update d/c ----
        for (int idx = tid; idx < nb * 128; idx += 512) {
            int b = idx >> 7, k = idx & 127;
            float s  = cx.ssb[2*b] + cx.ssb[2*b+1] + b2v * cx.sq[b];
            float yt = fmaf(cx.syp[b*128 + t], wfcy, s + bfcv);
            const float* zp = cx.szp + b * 512;
            float zi = zp[k]     + zp[3584 + k]     + zp[7168 + k]     + zp[10752 + k];
            float zf = zp[128+k] + zp[3584 + 128+k] + zp[7168 + 128+k] + zp[10752 + 128+k];
            float zg = zp[256+k] + zp[3584 + 256+k] + zp[7168 + 256+k] + zp[10752 + 256+k];
            float zo = zp[384+k] + zp[3584 + 384+k] + zp[7168 + 384+k] + zp[10752 + 384+k];
            zi = fmaf(yt, cx.sWx[k],     zi + cx.sbl[k]);
            zf = fmaf(yt, cx.sWx[128+k], zf + cx.sbl[128+k]);
            zg = fmaf(yt, cx.sWx[256+k], zg + cx.sbl[256+k]);
            zo = fmaf(yt, cx.sWx[384+k], zo + cx.sbl[384+k]);
            float cn = fmaf(sig_ap(zf), cx.sc[idx], sig_ap(zi) * tanh_ap(zg));
            cx.sc[idx] = cn;
            cx.sd[idx] = sig_ap(zo) * tanh_ap(cn);
        }
        __syncthreads();
    }

    // ---- Epilogue: ctx from final beta; out = d.Wf[:128] + ctx.Wf[128:] + bf ----
    if (wid < nb) {
        int b = wid;
        const float4* Xb = (const float4*)(X + (size_t)(b0 + b) * T1 * HE);
        float cxx = 0.f, cy = 0.f, cz = 0.f, cw = 0.f;
        for (int tp = 0; tp < T1; tp++) {
            float bb = cx.sbeta[b*128 + tp];
            float4 xv = Xb[tp*32 + lane];
            cxx = fmaf(bb, xv.x, cxx); cy = fmaf(bb, xv.y, cy);
            cz  = fmaf(bb, xv.z, cz);  cw = fmaf(bb, xv.w, cw);
        }
        float4 wfc2 = ((const float4*)(Wf + 128))[lane];
        float4 wfd  = ((const float4*)Wf)[lane];
        float4 dv   = ((const float4*)(cx.sd + b*128))[lane];
        float r = cxx*wfc2.x + cy*wfc2.y + cz*wfc2.z + cw*wfc2.w;
        r = fmaf(dv.x, wfd.x, r); r = fmaf(dv.y, wfd.y, r);
        r = fmaf(dv.z, wfd.z, r); r = fmaf(dv.w, wfd.w, r);
        #pragma unroll
        for (int m = 16; m; m >>= 1) r += __shfl_xor_sync(0xffffffffu, r, m);
        if (lane == 0) out[b0 + b] = r + bf[0];
    }
}

extern "C" void kernel_launch(void* const* d_in, const int* in_sizes, int n_in,
                              void* d_out, int out_size)
{
    const float* X    = (const float*)d_in[0];
    const float* yprev= (const float*)d_in[1];
    const float* W1   = (const float*)d_in[2];
    const float* b1   = (const float*)d_in[3];
    const float* W2   = (const float*)d_in[4];
    const float* b2   = (const float*)d_in[5];
    const float* Wfc  = (const float*)d_in[6];
    const float* bfc  = (const float*)d_in[7];
    const float* Wx   = (const float*)d_in[8];
    const float* Wh   = (const float*)d_in[9];
    const float* bl   = (const float*)d_in[10];
    const float* Wf   = (const float*)d_in[11];
    const float* bf   = (const float*)d_in[12];
    float* out = (float*)d_out;

    cudaFuncSetAttribute(prex_kernel, cudaFuncAttributeMaxDynamicSharedMemorySize, PRE_SMEM);
    cudaFuncSetAttribute(decoder_kernel, cudaFuncAttributeMaxDynamicSharedMemorySize, MAIN_SMEM);

    prex_kernel<<<BSZ, 256, PRE_SMEM>>>(X, W1, b1, Wfc);
    decoder_kernel<<<NCTA, 512, MAIN_SMEM>>>(X, yprev, W1, W2, b2, Wfc, bfc,
                                             Wx, Wh, bl, Wf, bf, out);
}

// round 4
// speedup vs baseline: 3.4836x; 1.1345x over previous
#include <cuda_runtime.h>
#include <cuda_fp16.h>
#include <math.h>

#define BSZ 1024
#define T1  127
#define TP  128      // padded time dim for g_prex
#define HD  128
#define HE  128
#define ZD  512
#define GMAX 7
#define NCTA 147     // 147*7 = 1029 >= 1024

// global scratch (allowed: __device__ arrays)
__device__ __half g_prex[(size_t)BSZ * TP * HE];   // 33.5 MB, L2-resident
__device__ float  g_px2[BSZ * T1];
__device__ __half g_whh[HD * ZD];                  // Wh in fp16, 128 KB

static __device__ __forceinline__ float tanh_ap(float x){
    float r; asm("tanh.approx.f32 %0, %1;" : "=f"(r) : "f"(x)); return r;
}
static __device__ __forceinline__ float sig_ap(float x){
    return fmaf(0.5f, tanh_ap(0.5f * x), 0.5f);
}

// packed f32x2 helpers
#define FMA2(d,a,b,c)  asm("fma.rn.f32x2 %0, %1, %2, %3;" : "=l"(d) : "l"(a), "l"(b), "l"(c))
#define PACKB(d,x)     asm("mov.b64 %0, {%1,%1};" : "=l"(d) : "f"(x))
#define PACK2(d,x,y)   asm("mov.b64 %0, {%1,%2};" : "=l"(d) : "f"(x), "f"(y))
#define UNPACK2(x,y,d) asm("mov.b64 {%0,%1}, %2;" : "=f"(x), "=f"(y) : "l"(d))

// ---------------------------------------------------------------------------
// Wh -> fp16 conversion (65536 elements)
// ---------------------------------------------------------------------------
__global__ void cvt_wh_kernel(const float* __restrict__ Wh)
{
    int i = blockIdx.x * 256 + threadIdx.x;
    g_whh[i] = __float2half(Wh[i]);
}

// ---------------------------------------------------------------------------
// Prepass: pre_x[b,t,e] = X[b,t,:]@W1_x + b1[e] (fp16, t padded to 128)
//          px2[b,t]     = X[b,t,:].Wfc[:128]
// ---------------------------------------------------------------------------
#define PRE_SMEM ((HD*HE + T1*HE) * 4)

__global__ void __launch_bounds__(256, 1)
prex_kernel(const float* __restrict__ X, const float* __restrict__ W1,
            const float* __restrict__ b1, const float* __restrict__ Wfc)
{
    extern __shared__ float sm[];
    float* sW = sm;            // 128*128
    float* sX = sm + HD * HE;  // 127*128
    int b = blockIdx.x;
    int tid = threadIdx.x, lane = tid & 31, wid = tid >> 5;
    const float* Xb = X + (size_t)b * T1 * HE;

    for (int i = tid; i < HD * HE; i += 256) sW[i] = W1[2 * HD * HE + i];
    for (int i = tid; i < T1 * HE; i += 256) sX[i] = Xb[i];
    __syncthreads();

    int e = tid & 127, th = tid >> 7;
    float b1e = b1[e];
    for (int t = th; t < T1; t += 2) {
        float acc = 0.f;
        const float* xr = sX + t * HE;
        #pragma unroll 8
        for (int k = 0; k < HE; k++) acc = fmaf(xr[k], sW[k * HE + e], acc);
        g_prex[((size_t)b * TP + t) * HE + e] = __float2half(acc + b1e);
    }
    if (tid < 128) g_prex[((size_t)b * TP + 127) * HE + tid] = __float2half(0.f);

    float4 wf = ((const float4*)Wfc)[lane];
    for (int t = wid; t < T1; t += 8) {
        float4 x = ((const float4*)(sX + t * HE))[lane];
        float p = x.x * wf.x + x.y * wf.y + x.z * wf.z + x.w * wf.w;
        #pragma unroll
        for (int m = 16; m; m >>= 1) p += __shfl_xor_sync(0xffffffffu, p, m);
        if (lane == 0) g_px2[b * T1 + t] = p;
    }
}

// ---------------------------------------------------------------------------
// Main persistent kernel: 147 CTAs x 7 batches x 512 threads, 127 steps
// ---------------------------------------------------------------------------
#define O_W1   0                      // 2*128*128 = 32768
#define O_VA   32768                  // A partials [4][7][128] = 3584
#define O_ZP   (O_VA + 3584)          // C partials [4][7][512] = 14336
#define O_D    (O_ZP + 14336)         // 896
#define O_C    (O_D + 896)            // 896
#define O_BETA (O_C + 896)            // 896
#define O_PX2  (O_BETA + 896)         // 896
#define O_YP   (O_PX2 + 896)          // 896
#define O_W2   (O_YP + 896)           // 128
#define O_WX   (O_W2 + 128)           // 512
#define O_BL   (O_WX + 512)           // 512
#define O_SSB  (O_BL + 512)           // 16
#define O_SQ   (O_SSB + 16)           // 8
#define MAIN_FLOATS (O_SQ + 8)
#define MAIN_SMEM (MAIN_FLOATS * 4)   // 225,376 B

struct Ctx {
    float* sW1; float* sva; float* szp; float* sd; float* sc; float* sbeta;
    float* spx2; float* syp; float* sW2; float* sWx; float* sbl; float* ssb; float* sq;
};

static __device__ __forceinline__ void phaseB(const Ctx& cx, int b0, int b, int half_,
                                              int lane, bool last, float b2v)
{
    float4 a0 = ((const float4*)(cx.sva + 0*896 + b*128))[lane];
    float4 a1 = ((const float4*)(cx.sva + 1*896 + b*128))[lane];
    float4 a2 = ((const float4*)(cx.sva + 2*896 + b*128))[lane];
    float4 a3 = ((const float4*)(cx.sva + 3*896 + b*128))[lane];
    float4 vr = make_float4(a0.x+a1.x+a2.x+a3.x, a0.y+a1.y+a2.y+a3.y,
                            a0.z+a1.z+a2.z+a3.z, a0.w+a1.w+a2.w+a3.w);
    float4 w2r = ((const float4*)cx.sW2)[lane];
    // row stride = 128 half = 32 uint2; lane covers e = 4*lane..4*lane+3
    const uint2* pxb = ((const uint2*)(g_prex + (size_t)(b0 + b) * TP * HE)) + lane;
    const float* px2b = cx.spx2 + b * 128;
    float s_l = 0.f;
    int tp0 = half_ * 64;

    uint2 c0 = pxb[(tp0+0)*32], c1 = pxb[(tp0+1)*32];
    uint2 c2 = pxb[(tp0+2)*32], c3 = pxb[(tp0+3)*32];

    #pragma unroll 1
    for (int tc = 0; tc < 64; tc += 4) {
        int tp = tp0 + tc;
        int tn = (tc + 4 < 64) ? tp + 4 : tp;   // last iter: redundant reload (hot)
        uint2 n0 = pxb[(tn+0)*32], n1 = pxb[(tn+1)*32];
        uint2 n2 = pxb[(tn+2)*32], n3 = pxb[(tn+3)*32];

        float2 f0a = __half22float2(*(const __half2*)&c0.x);
        float2 f0b = __half22float2(*(const __half2*)&c0.y);
        float2 f1a = __half22float2(*(const __half2*)&c1.x);
        float2 f1b = __half22float2(*(const __half2*)&c1.y);
        float2 f2a = __half22float2(*(const __half2*)&c2.x);
        float2 f2b = __half22float2(*(const __half2*)&c2.y);
        float2 f3a = __half22float2(*(const __half2*)&c3.x);
        float2 f3b = __half22float2(*(const __half2*)&c3.y);

        float pl0 = w2r.x*tanh_ap(f0a.x+vr.x); pl0 = fmaf(w2r.y, tanh_ap(f0a.y+vr.y), pl0);
        pl0 = fmaf(w2r.z, tanh_ap(f0b.x+vr.z), pl0); pl0 = fmaf(w2r.w, tanh_ap(f0b.y+vr.w), pl0);
        float pl1 = w2r.x*tanh_ap(f1a.x+vr.x); pl1 = fmaf(w2r.y, tanh_ap(f1a.y+vr.y), pl1);
        pl1 = fmaf(w2r.z, tanh_ap(f1b.x+vr.z), pl1); pl1 = fmaf(w2r.w, tanh_ap(f1b.y+vr.w), pl1);
        float pl2 = w2r.x*tanh_ap(f2a.x+vr.x); pl2 = fmaf(w2r.y, tanh_ap(f2a.y+vr.y), pl2);
        pl2 = fmaf(w2r.z, tanh_ap(f2b.x+vr.z), pl2); pl2 = fmaf(w2r.w, tanh_ap(f2b.y+vr.w), pl2);
        float pl3 = w2r.x*tanh_ap(f3a.x+vr.x); pl3 = fmaf(w2r.y, tanh_ap(f3a.y+vr.y), pl3);
        pl3 = fmaf(w2r.z, tanh_ap(f3b.x+vr.z), pl3); pl3 = fmaf(w2r.w, tanh_ap(f3b.y+vr.w), pl3);

        s_l = fmaf(pl0, px2b[tp+0], s_l);
        s_l = fmaf(pl1, px2b[tp+1], s_l);
        s_l = fmaf(pl2, px2b[tp+2], s_l);
        s_l = fmaf(pl3, px2b[tp+3], s_l);

        if (last) {
            float r0 = pl0, r1 = pl1, r2 = pl2, r3 = pl3;
            #pragma unroll
            for (int m = 16; m; m >>= 1) {
                r0 += __shfl_xor_sync(0xffffffffu, r0, m);
                r1 += __shfl_xor_sync(0xffffffffu, r1, m);
                r2 += __shfl_xor_sync(0xffffffffu, r2, m);
                r3 += __shfl_xor_sync(0xffffffffu, r3, m);
            }
            if (lane == 0) {
                cx.sbeta[b*128 + tp+0] = r0 + b2v;
                cx.sbeta[b*128 + tp+1] = r1 + b2v;
                cx.sbeta[b*128 + tp+2] = r2 + b2v;
                cx.sbeta[b*128 + tp+3] = r3 + b2v;
            }
        }
        c0 = n0; c1 = n1; c2 = n2; c3 = n3;
    }
    #pragma unroll
    for (int m = 16; m; m >>= 1) s_l += __shfl_xor_sync(0xffffffffu, s_l, m);
    if (lane == 0) cx.ssb[2*b + half_] = s_l;
}

static __device__ __forceinline__ void phaseC(const Ctx& cx, int tid, int nb)
{
    int jg = tid & 127, h = tid >> 7, kb = h * 32;
    const __half* whp = g_whh + (size_t)kb * ZD + jg * 4;   // 4 half j-values per row
    unsigned long long a01[GMAX], a23[GMAX];
    #pragma unroll
    for (int b = 0; b < GMAX; b++) { a01[b] = 0ULL; a23[b] = 0ULL; }

    uint2 wc0 = *(const uint2*)(whp + 0*ZD);
    uint2 wc1 = *(const uint2*)(whp + 1*ZD);
    uint2 wc2 = *(const uint2*)(whp + 2*ZD);
    uint2 wc3 = *(const uint2*)(whp + 3*ZD);

    #pragma unroll 1
    for (int kk = 0; kk < 32; kk += 4) {
        int kn = (kk + 4 < 32) ? kk + 4 : kk;
        uint2 n0 = *(const uint2*)(whp + (size_t)(kn+0)*ZD);
        uint2 n1 = *(const uint2*)(whp + (size_t)(kn+1)*ZD);
        uint2 n2 = *(const uint2*)(whp + (size_t)(kn+2)*ZD);
        uint2 n3 = *(const uint2*)(whp + (size_t)(kn+3)*ZD);

        // unpack weights to packed f32x2 (w01 = j0,j1 ; w23 = j2,j3) per row
        unsigned long long w01[4], w23[4];
        {
            float2 lo, hi;
            lo = __half22float2(*(const __half2*)&wc0.x); hi = __half22float2(*(const __half2*)&wc0.y);
            PACK2(w01[0], lo.x, lo.y); PACK2(w23[0], hi.x, hi.y);
            lo = __half22float2(*(const __half2*)&wc1.x); hi = __half22float2(*(const __half2*)&wc1.y);
            PACK2(w01[1], lo.x, lo.y); PACK2(w23[1], hi.x, hi.y);
            lo = __half22float2(*(const __half2*)&wc2.x); hi = __half22float2(*(const __half2*)&wc2.y);
            PACK2(w01[2], lo.x, lo.y); PACK2(w23[2], hi.x, hi.y);
            lo = __half22float2(*(const __half2*)&wc3.x); hi = __half22float2(*(const __half2*)&wc3.y);
            PACK2(w01[3], lo.x, lo.y); PACK2(w23[3], hi.x, hi.y);
        }
        #pragma unroll
        for (int b = 0; b < GMAX; b++) if (b < nb) {
            float4 dv = *(const float4*)(cx.sd + b*128 + kb + kk);
            unsigned long long dd;
            PACKB(dd, dv.x); FMA2(a01[b], dd, w01[0], a01[b]); FMA2(a23[b], dd, w23[0], a23[b]);
            PACKB(dd, dv.y); FMA2(a01[b], dd, w01[1], a01[b]); FMA2(a23[b], dd, w23[1], a23[b]);
            PACKB(dd, dv.z); FMA2(a01[b], dd, w01[2], a01[b]); FMA2(a23[b], dd, w23[2], a23[b]);
            PACKB(dd, dv.w); FMA2(a01[b], dd, w01[3], a01[b]); FMA2(a23[b], dd, w23[3], a23[b]);
        }
        wc0 = n0; wc1 = n1; wc2 = n2; wc3 = n3;
    }
    #pragma unroll
    for (int b = 0; b < GMAX; b++) if (b < nb) {
        float4 r;
        UNPACK2(r.x, r.y, a01[b]);
        UNPACK2(r.z, r.w, a23[b]);
        *(float4*)(cx.szp + h*3584 + b*512 + jg*4) = r;
    }
}

__global__ void __launch_bounds__(512, 1)
decoder_kernel(const float* __restrict__ X, const float* __restrict__ yprev,
               const float* __restrict__ W1, const float* __restrict__ W2,
               const float* __restrict__ b2, const float* __restrict__ Wfc,
               const float* __restrict__ bfc, const float* __restrict__ Wx,
               const float* __restrict__ Wh, const float* __restrict__ bl,
               const float* __restrict__ Wf, const float* __restrict__ bf,
               float* __restrict__ out)
{
    extern __shared__ float sm[];
    Ctx cx;
    cx.sW1 = sm + O_W1;  cx.sva = sm + O_VA;  cx.szp = sm + O_ZP;
    cx.sd = sm + O_D;    cx.sc = sm + O_C;    cx.sbeta = sm + O_BETA;
    cx.spx2 = sm + O_PX2; cx.syp = sm + O_YP; cx.sW2 = sm + O_W2;
    cx.sWx = sm + O_WX;  cx.sbl = sm + O_BL;  cx.ssb = sm + O_SSB; cx.sq = sm + O_SQ;

    int tid = threadIdx.x, lane = tid & 31, wid = tid >> 5;
    int b0 = blockIdx.x * GMAX;
    if (b0 >= BSZ) return;
    int nb = min(GMAX, BSZ - b0);

    for (int i = tid; i < 2 * HD * HE; i += 512) cx.sW1[i] = W1[i];
    if (tid < 128) cx.sW2[tid] = W2[tid];
    if (tid < 512) { cx.sWx[tid] = Wx[tid]; cx.sbl[tid] = bl[tid]; }
    for (int i = tid; i < nb * 128; i += 512) {
        int b = i >> 7, tp = i & 127;
        cx.spx2[i] = (tp < T1) ? g_px2[(b0 + b) * T1 + tp] : 0.f;
        cx.syp[i]  = (tp < T1) ? yprev[(size_t)(b0 + b) * T1 + tp] : 0.f;
        float x00 = X[(size_t)(b0 + b) * T1 * HE];
        cx.sd[i] = x00; cx.sc[i] = x00;
    }
    float b2v  = b2[0];
    float bfcv = bfc[0];
    float wfcy = Wfc[HE];
    __syncthreads();
    if (wid < nb) {   // step-invariant q_b = sum_t px2[b,t]
        const float* p = cx.spx2 + wid * 128;
        float v = p[lane] + p[lane+32] + p[lane+64] + p[lane+96];
        #pragma unroll
        for (int m = 16; m; m >>= 1) v += __shfl_xor_sync(0xffffffffu, v, m);
        if (lane == 0) cx.sq[wid] = v;
    }

    for (int t = 0; t < T1; t++) {
        // ---- Phase A: v partials = d@W1_d + c@W1_c, 4-way k-split ----
        {
            int e = tid & 127, h = tid >> 7, kb = h * 32;
            const float* wd = cx.sW1 + e;
            const float* wc = cx.sW1 + 128 * 128 + e;
            float acc[GMAX];
            #pragma unroll
            for (int b = 0; b < GMAX; b++) acc[b] = 0.f;
            #pragma unroll 2
            for (int kk = 0; kk < 32; kk += 4) {
                int k = kb + kk;
                float w0 = wd[k*128], w1 = wd[(k+1)*128], w2w = wd[(k+2)*128], w3 = wd[(k+3)*128];
                float u0 = wc[k*128], u1 = wc[(k+1)*128], u2 = wc[(k+2)*128], u3 = wc[(k+3)*128];
                #pragma unroll
                for (int b = 0; b < GMAX; b++) if (b < nb) {
                    float4 dv = *(const float4*)(cx.sd + b*128 + k);
                    float4 cv = *(const float4*)(cx.sc + b*128 + k);
                    float a = acc[b];
                    a = fmaf(dv.x, w0, a); a = fmaf(dv.y, w1, a);
                    a = fmaf(dv.z, w2w, a); a = fmaf(dv.w, w3, a);
                    a = fmaf(cv.x, u0, a); a = fmaf(cv.y, u1, a);
                    a = fmaf(cv.z, u2, a); a = fmaf(cv.w, u3, a);
                    acc[b] = a;
                }
            }
            #pragma unroll
            for (int b = 0; b < GMAX; b++) if (b < nb) cx.sva[h*896 + b*128 + e] = acc[b];
        }
        __syncthreads();

        // ---- Merged B (attention, MUFU) + C (d@Wh, FMA f32x2) with warp stagger ----
        {
            bool doB = (wid < 2 * nb);
            int b = wid >> 1, half_ = wid & 1;
            bool last = (t == T1 - 1);
            if (wid & 1) {
                phaseC(cx, tid, nb);
                if (doB) phaseB(cx, b0, b, half_, lane, last, b2v);
            } else {
                if (doB) phaseB(cx, b0, b, half_, lane, last, b2v);
                phaseC(cx, tid, nb);
            }
        }
        __syncthreads();

        // ---- Phase D: assemble z, gates, update d/c ----
        for (int idx = tid; idx < nb * 128; idx += 512) {
            int b = idx >> 7, k = idx & 127;
            float s  = cx.ssb[2*b] + cx.ssb[2*b+1] + b2v * cx.sq[b];
            float yt = fmaf(cx.syp[b*128 + t], wfcy, s + bfcv);
            const float* zp = cx.szp + b * 512;
            float zi = zp[k]     + zp[3584 + k]     + zp[7168 + k]     + zp[10752 + k];
            float zf = zp[128+k] + zp[3584 + 128+k] + zp[7168 + 128+k] + zp[10752 + 128+k];
            float zg = zp[256+k] + zp[3584 + 256+k] + zp[7168 + 256+k] + zp[10752 + 256+k];
            float zo = zp[384+k] + zp[3584 + 384+k] + zp[7168 + 384+k] + zp[10752 + 384+k];
            zi = fmaf(yt, cx.sWx[k],     zi + cx.sbl[k]);
            zf = fmaf(yt, cx.sWx[128+k], zf + cx.sbl[128+k]);
            zg = fmaf(yt, cx.sWx[256+k], zg + cx.sbl[256+k]);
            zo = fmaf(yt, cx.sWx[384+k], zo + cx.sbl[384+k]);
            float cn = fmaf(sig_ap(zf), cx.sc[idx], sig_ap(zi) * tanh_ap(zg));
            cx.sc[idx] = cn;
            cx.sd[idx] = sig_ap(zo) * tanh_ap(cn);
        }
        __syncthreads();
    }

    // ---- Epilogue: ctx from final beta; out = d.Wf[:128] + ctx.Wf[128:] + bf ----
    if (wid < nb) {
        int b = wid;
        const float4* Xb = (const float4*)(X + (size_t)(b0 + b) * T1 * HE);
        float cxx = 0.f, cy = 0.f, cz = 0.f, cw = 0.f;
        for (int tp = 0; tp < T1; tp++) {
            float bb = cx.sbeta[b*128 + tp];
            float4 xv = Xb[tp*32 + lane];
            cxx = fmaf(bb, xv.x, cxx); cy = fmaf(bb, xv.y, cy);
            cz  = fmaf(bb, xv.z, cz);  cw = fmaf(bb, xv.w, cw);
        }
        float4 wfc2 = ((const float4*)(Wf + 128))[lane];
        float4 wfd  = ((const float4*)Wf)[lane];
        float4 dv   = ((const float4*)(cx.sd + b*128))[lane];
        float r = cxx*wfc2.x + cy*wfc2.y + cz*wfc2.z + cw*wfc2.w;
        r = fmaf(dv.x, wfd.x, r); r = fmaf(dv.y, wfd.y, r);
        r = fmaf(dv.z, wfd.z, r); r = fmaf(dv.w, wfd.w, r);
        #pragma unroll
        for (int m = 16; m; m >>= 1) r += __shfl_xor_sync(0xffffffffu, r, m);
        if (lane == 0) out[b0 + b] = r + bf[0];
    }
}

extern "C" void kernel_launch(void* const* d_in, const int* in_sizes, int n_in,
                              void* d_out, int out_size)
{
    const float* X    = (const float*)d_in[0];
    const float* yprev= (const float*)d_in[1];
    const float* W1   = (const float*)d_in[2];
    const float* b1   = (const float*)d_in[3];
    const float* W2   = (const float*)d_in[4];
    const float* b2   = (const float*)d_in[5];
    const float* Wfc  = (const float*)d_in[6];
    const float* bfc  = (const float*)d_in[7];
    const float* Wx   = (const float*)d_in[8];
    const float* Wh   = (const float*)d_in[9];
    const float* bl   = (const float*)d_in[10];
    const float* Wf   = (const float*)d_in[11];
    const float* bf   = (const float*)d_in[12];
    float* out = (float*)d_out;

    cudaFuncSetAttribute(prex_kernel, cudaFuncAttributeMaxDynamicSharedMemorySize, PRE_SMEM);
    cudaFuncSetAttribute(decoder_kernel, cudaFuncAttributeMaxDynamicSharedMemorySize, MAIN_SMEM);

    cvt_wh_kernel<<<HD * ZD / 256, 256>>>(Wh);
    prex_kernel<<<BSZ, 256, PRE_SMEM>>>(X, W1, b1, Wfc);
    decoder_kernel<<<NCTA, 512, MAIN_SMEM>>>(X, yprev, W1, W2, b2, Wfc, bfc,
                                             Wx, Wh, bl, Wf, bf, out);
}

// round 6
// speedup vs baseline: 3.4898x; 1.0018x over previous
#include <cuda_runtime.h>
#include <cuda_fp16.h>
#include <math.h>

#define BSZ 1024
#define T1  127
#define TP  128      // padded time dim for g_prex
#define HD  128
#define HE  128
#define ZD  512
#define GMAX 7
#define NCTA 147     // 147*7 = 1029 >= 1024

// global scratch (allowed: __device__ arrays)
__device__ __half g_prex[(size_t)BSZ * TP * HE];   // 33.5 MB, L2-resident
__device__ float  g_px2[BSZ * T1];
__device__ __half g_whh[HD * ZD];                  // Wh in fp16, 128 KB

static __device__ __forceinline__ float tanh_ap(float x){
    float r; asm("tanh.approx.f32 %0, %1;" : "=f"(r) : "f"(x)); return r;
}
static __device__ __forceinline__ float sig_ap(float x){
    return fmaf(0.5f, tanh_ap(0.5f * x), 0.5f);
}
// f16x2 tanh on a bit-packed half2
static __device__ __forceinline__ unsigned tanh2_ap(unsigned x){
    unsigned r; asm("tanh.approx.f16x2 %0, %1;" : "=r"(r) : "r"(x)); return r;
}
static __device__ __forceinline__ unsigned h2u(__half2 h){
    union { __half2 h; unsigned u; } v; v.h = h; return v.u;
}
static __device__ __forceinline__ __half2 u2h(unsigned u){
    union { __half2 h; unsigned u; } v; v.u = u; return v.h;
}

// packed f32x2 helpers
#define FMA2(d,a,b,c)  asm("fma.rn.f32x2 %0, %1, %2, %3;" : "=l"(d) : "l"(a), "l"(b), "l"(c))
#define PACKB(d,x)     asm("mov.b64 %0, {%1,%1};" : "=l"(d) : "f"(x))
#define PACK2(d,x,y)   asm("mov.b64 %0, {%1,%2};" : "=l"(d) : "f"(x), "f"(y))
#define UNPACK2(x,y,d) asm("mov.b64 {%0,%1}, %2;" : "=f"(x), "=f"(y) : "l"(d))

// ---------------------------------------------------------------------------
// Wh -> fp16 conversion (65536 elements)
// ---------------------------------------------------------------------------
__global__ void cvt_wh_kernel(const float* __restrict__ Wh)
{
    int i = blockIdx.x * 256 + threadIdx.x;
    g_whh[i] = __float2half(Wh[i]);
}

// ---------------------------------------------------------------------------
// Prepass: pre_x[b,t,e] = X[b,t,:]@W1_x + b1[e] (fp16, t padded to 128)
//          px2[b,t]     = X[b,t,:].Wfc[:128]
// ---------------------------------------------------------------------------
#define PRE_SMEM ((HD*HE + T1*HE) * 4)

__global__ void __launch_bounds__(256, 1)
prex_kernel(const float* __restrict__ X, const float* __restrict__ W1,
            const float* __restrict__ b1, const float* __restrict__ Wfc)
{
    extern __shared__ float sm[];
    float* sW = sm;            // 128*128
    float* sX = sm + HD * HE;  // 127*128
    int b = blockIdx.x;
    int tid = threadIdx.x, lane = tid & 31, wid = tid >> 5;
    const float* Xb = X + (size_t)b * T1 * HE;

    for (int i = tid; i < HD * HE; i += 256) sW[i] = W1[2 * HD * HE + i];
    for (int i = tid; i < T1 * HE; i += 256) sX[i] = Xb[i];
    __syncthreads();

    int e = tid & 127, th = tid >> 7;
    float b1e = b1[e];
    for (int t = th; t < T1; t += 2) {
        float acc = 0.f;
        const float* xr = sX + t * HE;
        #pragma unroll 8
        for (int k = 0; k < HE; k++) acc = fmaf(xr[k], sW[k * HE + e], acc);
        g_prex[((size_t)b * TP + t) * HE + e] = __float2half(acc + b1e);
    }
    if (tid < 128) g_prex[((size_t)b * TP + 127) * HE + tid] = __float2half(0.f);

    float4 wf = ((const float4*)Wfc)[lane];
    for (int t = wid; t < T1; t += 8) {
        float4 x = ((const float4*)(sX + t * HE))[lane];
        float p = x.x * wf.x + x.y * wf.y + x.z * wf.z + x.w * wf.w;
        #pragma unroll
        for (int m = 16; m; m >>= 1) p += __shfl_xor_sync(0xffffffffu, p, m);
        if (lane == 0) g_px2[b * T1 + t] = p;
    }
}

// ---------------------------------------------------------------------------
// Main persistent kernel: 147 CTAs x 7 batches x 512 threads, 127 steps
// ---------------------------------------------------------------------------
#define O_W1   0                      // 2*128*128 = 32768
#define O_VA   32768                  // A partials [4][7][128] = 3584
#define O_ZP   (O_VA + 3584)          // C partials [4][7][512] = 14336
#define O_D    (O_ZP + 14336)         // 896
#define O_C    (O_D + 896)            // 896
#define O_BETA (O_C + 896)            // 896
#define O_PX2  (O_BETA + 896)         // 896
#define O_YP   (O_PX2 + 896)          // 896
#define O_W2   (O_YP + 896)           // 128
#define O_WX   (O_W2 + 128)           // 512
#define O_BL   (O_WX + 512)           // 512
#define O_SSB  (O_BL + 512)           // 16
#define O_SQ   (O_SSB + 16)           // 8
#define MAIN_FLOATS (O_SQ + 8)
#define MAIN_SMEM (MAIN_FLOATS * 4)   // 225,376 B

struct Ctx {
    float* sW1; float* sva; float* szp; float* sd; float* sc; float* sbeta;
    float* spx2; float* syp; float* sW2; float* sWx; float* sbl; float* ssb; float* sq;
};

static __device__ __forceinline__ void phaseB(const Ctx& cx, int b0, int b, int half_,
                                              int lane, bool last, float b2v)
{
    float4 a0 = ((const float4*)(cx.sva + 0*896 + b*128))[lane];
    float4 a1 = ((const float4*)(cx.sva + 1*896 + b*128))[lane];
    float4 a2 = ((const float4*)(cx.sva + 2*896 + b*128))[lane];
    float4 a3 = ((const float4*)(cx.sva + 3*896 + b*128))[lane];
    float4 vr = make_float4(a0.x+a1.x+a2.x+a3.x, a0.y+a1.y+a2.y+a3.y,
                            a0.z+a1.z+a2.z+a3.z, a0.w+a1.w+a2.w+a3.w);
    float4 w2r = ((const float4*)cx.sW2)[lane];
    __half2 vr01 = __floats2half2_rn(vr.x, vr.y);
    __half2 vr23 = __floats2half2_rn(vr.z, vr.w);
    __half2 w01  = __floats2half2_rn(w2r.x, w2r.y);
    __half2 w23  = __floats2half2_rn(w2r.z, w2r.w);

    // row stride = 128 half = 32 uint2; lane covers e = 4*lane..4*lane+3
    const uint2* pxb = ((const uint2*)(g_prex + (size_t)(b0 + b) * TP * HE)) + lane;
    const float* px2b = cx.spx2 + b * 128;
    float s_l = 0.f;
    int tp0 = half_ * 64;

    uint2 c0 = pxb[(tp0+0)*32], c1 = pxb[(tp0+1)*32];
    uint2 c2 = pxb[(tp0+2)*32], c3 = pxb[(tp0+3)*32];

    #pragma unroll 1
    for (int tc = 0; tc < 64; tc += 4) {
        int tp = tp0 + tc;
        int tn = (tc + 4 < 64) ? tp + 4 : tp;   // last iter: redundant reload (hot)
        uint2 n0 = pxb[(tn+0)*32], n1 = pxb[(tn+1)*32];
        uint2 n2 = pxb[(tn+2)*32], n3 = pxb[(tn+3)*32];

        __half2 h0a = u2h(tanh2_ap(h2u(__hadd2(u2h(c0.x), vr01))));
        __half2 h0b = u2h(tanh2_ap(h2u(__hadd2(u2h(c0.y), vr23))));
        __half2 h1a = u2h(tanh2_ap(h2u(__hadd2(u2h(c1.x), vr01))));
        __half2 h1b = u2h(tanh2_ap(h2u(__hadd2(u2h(c1.y), vr23))));
        __half2 h2a = u2h(tanh2_ap(h2u(__hadd2(u2h(c2.x), vr01))));
        __half2 h2b = u2h(tanh2_ap(h2u(__hadd2(u2h(c2.y), vr23))));
        __half2 h3a = u2h(tanh2_ap(h2u(__hadd2(u2h(c3.x), vr01))));
        __half2 h3b = u2h(tanh2_ap(h2u(__hadd2(u2h(c3.y), vr23))));

        __half2 p0 = __hfma2(h0b, w23, __hmul2(h0a, w01));
        __half2 p1 = __hfma2(h1b, w23, __hmul2(h1a, w01));
        __half2 p2 = __hfma2(h2b, w23, __hmul2(h2a, w01));
        __half2 p3 = __hfma2(h3b, w23, __hmul2(h3a, w01));
        float2 q0 = __half22float2(p0);
        float2 q1 = __half22float2(p1);
        float2 q2 = __half22float2(p2);
        float2 q3 = __half22float2(p3);
        float pl0 = q0.x + q0.y, pl1 = q1.x + q1.y;
        float pl2 = q2.x + q2.y, pl3 = q3.x + q3.y;

        s_l = fmaf(pl0, px2b[tp+0], s_l);
        s_l = fmaf(pl1, px2b[tp+1], s_l);
        s_l = fmaf(pl2, px2b[tp+2], s_l);
        s_l = fmaf(pl3, px2b[tp+3], s_l);

        if (last) {
            float r0 = pl0, r1 = pl1, r2 = pl2, r3 = pl3;
            #pragma unroll
            for (int m = 16; m; m >>= 1) {
                r0 += __shfl_xor_sync(0xffffffffu, r0, m);
                r1 += __shfl_xor_sync(0xffffffffu, r1, m);
                r2 += __shfl_xor_sync(0xffffffffu, r2, m);
                r3 += __shfl_xor_sync(0xffffffffu, r3, m);
            }
            if (lane == 0) {
                cx.sbeta[b*128 + tp+0] = r0 + b2v;
                cx.sbeta[b*128 + tp+1] = r1 + b2v;
                cx.sbeta[b*128 + tp+2] = r2 + b2v;
                cx.sbeta[b*128 + tp+3] = r3 + b2v;
            }
        }
        c0 = n0; c1 = n1; c2 = n2; c3 = n3;
    }
    #pragma unroll
    for (int m = 16; m; m >>= 1) s_l += __shfl_xor_sync(0xffffffffu, s_l, m);
    if (lane == 0) cx.ssb[2*b + half_] = s_l;
}

static __device__ __forceinline__ void phaseC(const Ctx& cx, int tid, int nb)
{
    int jg = tid & 127, h = tid >> 7, kb = h * 32;
    const __half* whp = g_whh + (size_t)kb * ZD + jg * 4;   // 4 half j-values per row
    unsigned long long a01[GMAX], a23[GMAX];
    #pragma unroll
    for (int b = 0; b < GMAX; b++) { a01[b] = 0ULL; a23[b] = 0ULL; }

    uint2 wc0 = *(const uint2*)(whp + 0*ZD);
    uint2 wc1 = *(const uint2*)(whp + 1*ZD);
    uint2 wc2 = *(const uint2*)(whp + 2*ZD);
    uint2 wc3 = *(const uint2*)(whp + 3*ZD);

    #pragma unroll 1
    for (int kk = 0; kk < 32; kk += 4) {
        int kn = (kk + 4 < 32) ? kk + 4 : kk;
        uint2 n0 = *(const uint2*)(whp + (size_t)(kn+0)*ZD);
        uint2 n1 = *(const uint2*)(whp + (size_t)(kn+1)*ZD);
        uint2 n2 = *(const uint2*)(whp + (size_t)(kn+2)*ZD);
        uint2 n3 = *(const uint2*)(whp + (size_t)(kn+3)*ZD);

        unsigned long long w01[4], w23[4];
        {
            float2 lo, hi;
            lo = __half22float2(u2h(wc0.x)); hi = __half22float2(u2h(wc0.y));
            PACK2(w01[0], lo.x, lo.y); PACK2(w23[0], hi.x, hi.y);
            lo = __half22float2(u2h(wc1.x)); hi = __half22float2(u2h(wc1.y));
            PACK2(w01[1], lo.x, lo.y); PACK2(w23[1], hi.x, hi.y);
            lo = __half22float2(u2h(wc2.x)); hi = __half22float2(u2h(wc2.y));
            PACK2(w01[2], lo.x, lo.y); PACK2(w23[2], hi.x, hi.y);
            lo = __half22float2(u2h(wc3.x)); hi = __half22float2(u2h(wc3.y));
            PACK2(w01[3], lo.x, lo.y); PACK2(w23[3], hi.x, hi.y);
        }
        #pragma unroll
        for (int b = 0; b < GMAX; b++) if (b < nb) {
            float4 dv = *(const float4*)(cx.sd + b*128 + kb + kk);
            unsigned long long dd;
            PACKB(dd, dv.x); FMA2(a01[b], dd, w01[0], a01[b]); FMA2(a23[b], dd, w23[0], a23[b]);
            PACKB(dd, dv.y); FMA2(a01[b], dd, w01[1], a01[b]); FMA2(a23[b], dd, w23[1], a23[b]);
            PACKB(dd, dv.z); FMA2(a01[b], dd, w01[2], a01[b]); FMA2(a23[b], dd, w23[2], a23[b]);
            PACKB(dd, dv.w); FMA2(a01[b], dd, w01[3], a01[b]); FMA2(a23[b], dd, w23[3], a23[b]);
        }
        wc0 = n0; wc1 = n1; wc2 = n2; wc3 = n3;
    }
    #pragma unroll
    for (int b = 0; b < GMAX; b++) if (b < nb) {
        float4 r;
        UNPACK2(r.x, r.y, a01[b]);
        UNPACK2(r.z, r.w, a23[b]);
        *(float4*)(cx.szp + h*3584 + b*512 + jg*4) = r;
    }
}

__global__ void __launch_bounds__(512, 1)
decoder_kernel(const float* __restrict__ X, const float* __restrict__ yprev,
               const float* __restrict__ W1, const float* __restrict__ W2,
               const float* __restrict__ b2, const float* __restrict__ Wfc,
               const float* __restrict__ bfc, const float* __restrict__ Wx,
               const float* __restrict__ Wh, const float* __restrict__ bl,
               const float* __restrict__ Wf, const float* __restrict__ bf,
               float* __restrict__ out)
{
    extern __shared__ float sm[];
    Ctx cx;
    cx.sW1 = sm + O_W1;  cx.sva = sm + O_VA;  cx.szp = sm + O_ZP;
    cx.sd = sm + O_D;    cx.sc = sm + O_C;    cx.sbeta = sm + O_BETA;
    cx.spx2 = sm + O_PX2; cx.syp = sm + O_YP; cx.sW2 = sm + O_W2;
    cx.sWx = sm + O_WX;  cx.sbl = sm + O_BL;  cx.ssb = sm + O_SSB; cx.sq = sm + O_SQ;

    int tid = threadIdx.x, lane = tid & 31, wid = tid >> 5;
    int b0 = blockIdx.x * GMAX;
    if (b0 >= BSZ) return;
    int nb = min(GMAX, BSZ - b0);

    for (int i = tid; i < 2 * HD * HE; i += 512) cx.sW1[i] = W1[i];
    if (tid < 128) cx.sW2[tid] = W2[tid];
    if (tid < 512) { cx.sWx[tid] = Wx[tid]; cx.sbl[tid] = bl[tid]; }
    for (int i = tid; i < nb * 128; i += 512) {
        int b = i >> 7, tp = i & 127;
        cx.spx2[i] = (tp < T1) ? g_px2[(b0 + b) * T1 + tp] : 0.f;
        cx.syp[i]  = (tp < T1) ? yprev[(size_t)(b0 + b) * T1 + tp] : 0.f;
        float x00 = X[(size_t)(b0 + b) * T1 * HE];
        cx.sd[i] = x00; cx.sc[i] = x00;
    }
    float b2v  = b2[0];
    float bfcv = bfc[0];
    float wfcy = Wfc[HE];
    __syncthreads();
    if (wid < nb) {   // step-invariant q_b = sum_t px2[b,t]
        const float* p = cx.spx2 + wid * 128;
        float v = p[lane] + p[lane+32] + p[lane+64] + p[lane+96];
        #pragma unroll
        for (int m = 16; m; m >>= 1) v += __shfl_xor_sync(0xffffffffu, v, m);
        if (lane == 0) cx.sq[wid] = v;
    }

    for (int t = 0; t < T1; t++) {
        // ---- Phase A: v partials = d@W1_d + c@W1_c, 4-way k-split ----
        {
            int e = tid & 127, h = tid >> 7, kb = h * 32;
            const float* wd = cx.sW1 + e;
            const float* wc = cx.sW1 + 128 * 128 + e;
            float acc[GMAX];
            #pragma unroll
            for (int b = 0; b < GMAX; b++) acc[b] = 0.f;
            #pragma unroll 2
            for (int kk = 0; kk < 32; kk += 4) {
                int k = kb + kk;
                float w0 = wd[k*128], w1 = wd[(k+1)*128], w2w = wd[(k+2)*128], w3 = wd[(k+3)*128];
                float u0 = wc[k*128], u1 = wc[(k+1)*128], u2 = wc[(k+2)*128], u3 = wc[(k+3)*128];
                #pragma unroll
                for (int b = 0; b < GMAX; b++) if (b < nb) {
                    float4 dv = *(const float4*)(cx.sd + b*128 + k);
                    float4 cv = *(const float4*)(cx.sc + b*128 + k);
                    float a = acc[b];
                    a = fmaf(dv.x, w0, a); a = fmaf(dv.y, w1, a);
                    a = fmaf(dv.z, w2w, a); a = fmaf(dv.w, w3, a);
                    a = fmaf(cv.x, u0, a); a = fmaf(cv.y, u1, a);
                    a = fmaf(cv.z, u2, a); a = fmaf(cv.w, u3, a);
                    acc[b] = a;
                }
            }
            #pragma unroll
            for (int b = 0; b < GMAX; b++) if (b < nb) cx.sva[h*896 + b*128 + e] = acc[b];
        }
        __syncthreads();

        // ---- Merged B (attention, f16x2) + C (d@Wh, FMA f32x2) with warp stagger ----
        {
            bool doB = (wid < 2 * nb);
            int b = wid >> 1, half_ = wid & 1;
            bool last = (t == T1 - 1);
            if (wid & 1) {
                phaseC(cx, tid, nb);
                if (doB) phaseB(cx, b0, b, half_, lane, last, b2v);
            } else {
                if (doB) phaseB(cx, b0, b, half_, lane, last, b2v);
                phaseC(cx, tid, nb);
            }
        }
        __syncthreads();

        // ---- Phase D: assemble z, gates, update d/c ----
        for (int idx = tid; idx < nb * 128; idx += 512) {
            int b = idx >> 7, k = idx & 127;
            float s  = cx.ssb[2*b] + cx.ssb[2*b+1] + b2v * cx.sq[b];
            float yt = fmaf(cx.syp[b*128 + t], wfcy, s + bfcv);
            const float* zp = cx.szp + b * 512;
            float zi = zp[k]     + zp[3584 + k]     + zp[7168 + k]     + zp[10752 + k];
            float zf = zp[128+k] + zp[3584 + 128+k] + zp[7168 + 128+k] + zp[10752 + 128+k];
            float zg = zp[256+k] + zp[3584 + 256+k] + zp[7168 + 256+k] + zp[10752 + 256+k];
            float zo = zp[384+k] + zp[3584 + 384+k] + zp[7168 + 384+k] + zp[10752 + 384+k];
            zi = fmaf(yt, cx.sWx[k],     zi + cx.sbl[k]);
            zf = fmaf(yt, cx.sWx[128+k], zf + cx.sbl[128+k]);
            zg = fmaf(yt, cx.sWx[256+k], zg + cx.sbl[256+k]);
            zo = fmaf(yt, cx.sWx[384+k], zo + cx.sbl[384+k]);
            float cn = fmaf(sig_ap(zf), cx.sc[idx], sig_ap(zi) * tanh_ap(zg));
            cx.sc[idx] = cn;
            cx.sd[idx] = sig_ap(zo) * tanh_ap(cn);
        }
        __syncthreads();
    }

    // ---- Epilogue: ctx from final beta; out = d.Wf[:128] + ctx.Wf[128:] + bf ----
    if (wid < nb) {
        int b = wid;
        const float4* Xb = (const float4*)(X + (size_t)(b0 + b) * T1 * HE);
        float cxx = 0.f, cy = 0.f, cz = 0.f, cw = 0.f;
        for (int tp = 0; tp < T1; tp++) {
            float bb = cx.sbeta[b*128 + tp];
            float4 xv = Xb[tp*32 + lane];
            cxx = fmaf(bb, xv.x, cxx); cy = fmaf(bb, xv.y, cy);
            cz  = fmaf(bb, xv.z, cz);  cw = fmaf(bb, xv.w, cw);
        }
        float4 wfc2 = ((const float4*)(Wf + 128))[lane];
        float4 wfd  = ((const float4*)Wf)[lane];
        float4 dv   = ((const float4*)(cx.sd + b*128))[lane];
        float r = cxx*wfc2.x + cy*wfc2.y + cz*wfc2.z + cw*wfc2.w;
        r = fmaf(dv.x, wfd.x, r); r = fmaf(dv.y, wfd.y, r);
        r = fmaf(dv.z, wfd.z, r); r = fmaf(dv.w, wfd.w, r);
        #pragma unroll
        for (int m = 16; m; m >>= 1) r += __shfl_xor_sync(0xffffffffu, r, m);
        if (lane == 0) out[b0 + b] = r + bf[0];
    }
}

extern "C" void kernel_launch(void* const* d_in, const int* in_sizes, int n_in,
                              void* d_out, int out_size)
{
    const float* X    = (const float*)d_in[0];
    const float* yprev= (const float*)d_in[1];
    const float* W1   = (const float*)d_in[2];
    const float* b1   = (const float*)d_in[3];
    const float* W2   = (const float*)d_in[4];
    const float* b2   = (const float*)d_in[5];
    const float* Wfc  = (const float*)d_in[6];
    const float* bfc  = (const float*)d_in[7];
    const float* Wx   = (const float*)d_in[8];
    const float* Wh   = (const float*)d_in[9];
    const float* bl   = (const float*)d_in[10];
    const float* Wf   = (const float*)d_in[11];
    const float* bf   = (const float*)d_in[12];
    float* out = (float*)d_out;

    cudaFuncSetAttribute(prex_kernel, cudaFuncAttributeMaxDynamicSharedMemorySize, PRE_SMEM);
    cudaFuncSetAttribute(decoder_kernel, cudaFuncAttributeMaxDynamicSharedMemorySize, MAIN_SMEM);

    cvt_wh_kernel<<<HD * ZD / 256, 256>>>(Wh);
    prex_kernel<<<BSZ, 256, PRE_SMEM>>>(X, W1, b1, Wfc);
    decoder_kernel<<<NCTA, 512, MAIN_SMEM>>>(X, yprev, W1, W2, b2, Wfc, bfc,
                                             Wx, Wh, bl, Wf, bf, out);
}